// round 15
// baseline (speedup 1.0000x reference)
#include <cuda_runtime.h>
#include <cuda_bf16.h>
#include <cstdint>

// VolumeRenderer: NeRF alpha-compositing.
// Output layout (tuple flattened): color[3N] | depth[N] | acc[N] | weights[192N]
//
// One warp per ray, 6 samples/lane (blocked). R6 skeleton:
//  - rgb prefetched via cp.async (coalesced 16B chunks, zero regs, latency
//    hidden behind the exp/scan chain)
//  - depth/sigma: direct strided LDG.64 into blocked registers (critical path)
// New this round:
//  - sigmoid via MUFU.TANH (1 MUFU instead of EX2+RCP): 7 -> 4 MUFU/sample
//  - weights staged blocked->smem, stored as coalesced STG.128 with __stcs
//    streaming hint (evict-first; protects L2 for the read stream)

#define NS   192
#define SPT  6
#define WPB  8
#define EPSV 1e-10f
#define BORDER 1e10f
#define FULLM 0xffffffffu

__device__ __forceinline__ float fsigmoid(float x) {
    // sigmoid(x) = 0.5*tanh(0.5x) + 0.5 ; MUFU.TANH rel err ~2^-11 << 1e-3 budget
    float th;
    asm("tanh.approx.f32 %0, %1;" : "=f"(th) : "f"(0.5f * x));
    return fmaf(0.5f, th, 0.5f);
}

__device__ __forceinline__ void cpa16(unsigned sdst, const char* gsrc) {
    asm volatile("cp.async.cg.shared.global [%0], [%1], 16;"
                 :: "r"(sdst), "l"(gsrc));
}

__global__ void __launch_bounds__(256)
vr_kernel(const float* __restrict__ depth,
          const float* __restrict__ rgb,
          const float* __restrict__ sigma,
          float* __restrict__ out,
          int n_rays)
{
    __shared__ __align__(16) float sRGB[WPB][NS * 3];  // 2304 B/warp
    __shared__ __align__(16) float sW[WPB][NS];        // 768 B/warp (weights restage)

    const int wi   = threadIdx.x >> 5;
    const int lane = threadIdx.x & 31;
    const int ray  = blockIdx.x * WPB + wi;
    if (ray >= n_rays) return;            // warp-uniform
    const long base = (long)ray * NS;

    // ---- 1. prefetch rgb into smem: 144 x 16B coalesced LDGSTS ----
    {
        const char* gr = reinterpret_cast<const char*>(rgb + base * 3);
        unsigned sr = (unsigned)__cvta_generic_to_shared(&sRGB[wi][0]);
        #pragma unroll
        for (int k = 0; k < 4; k++)
            cpa16(sr + (k * 32 + lane) * 16, gr + (long)(k * 32 + lane) * 16);
        if (lane < 16)
            cpa16(sr + (128 + lane) * 16, gr + (long)(128 + lane) * 16);
        asm volatile("cp.async.commit_group;" ::: "memory");
    }

    // ---- 2. depth / sigma: direct strided loads into blocked registers ----
    float d[SPT], sg[SPT];
    {
        const float2* dp = reinterpret_cast<const float2*>(depth + base + lane * SPT);
        const float2* sp = reinterpret_cast<const float2*>(sigma + base + lane * SPT);
        #pragma unroll
        for (int j = 0; j < 3; j++) { float2 v = dp[j]; d[2*j]  = v.x; d[2*j+1]  = v.y; }
        #pragma unroll
        for (int j = 0; j < 3; j++) { float2 v = sp[j]; sg[2*j] = v.x; sg[2*j+1] = v.y; }
    }

    const float dnext = __shfl_down_sync(FULLM, d[0], 1);

    // ---- 3. alpha / survival, local product ----
    float e[SPT];
    float p = 1.0f;
    #pragma unroll
    for (int j = 0; j < SPT; j++) {
        float dn = (j < SPT - 1) ? d[j + 1] : dnext;
        float delta = dn - d[j];
        if (lane == 31 && j == SPT - 1) delta = BORDER;
        float s = fmaxf(sg[j], 0.0f);
        float ex = __expf(-s * delta);
        e[j] = ex;
        p *= (ex + EPSV);
    }

    // ---- 4. warp multiplicative scan -> exclusive transmittance ----
    float incl = p;
    #pragma unroll
    for (int off = 1; off < 32; off <<= 1) {
        float v = __shfl_up_sync(FULLM, incl, off);
        if (lane >= off) incl *= v;
    }
    float t = __shfl_up_sync(FULLM, incl, 1);
    if (lane == 0) t = 1.0f;

    // ---- 5. weights + depth/acc; stage weights blocked into sW ----
    float acc = 0.0f, dep = 0.0f;
    #pragma unroll
    for (int j = 0; j < SPT; j++) {
        float wj = (1.0f - e[j]) * t;
        t *= (e[j] + EPSV);
        e[j] = wj;                           // reuse e[] as w[]
        acc += wj;
        dep = fmaf(wj, d[j], dep);
    }
    {
        float2* wa = reinterpret_cast<float2*>(&sW[wi][lane * SPT]);
        #pragma unroll
        for (int j = 0; j < 3; j++) wa[j] = make_float2(e[2*j], e[2*j+1]);
    }

    // ---- 6. rgb landed long ago; make it visible ----
    asm volatile("cp.async.wait_group 0;" ::: "memory");
    __syncwarp();

    // ---- 7. color pass (blocked rgb view, natural channel order) ----
    float c0 = 0.0f, c1 = 0.0f, c2 = 0.0f;
    {
        const float* rv = &sRGB[wi][lane * (SPT * 3)];
        #pragma unroll
        for (int j = 0; j < SPT; j++) {
            float wj = e[j];
            c0 = fmaf(wj, fsigmoid(rv[3*j + 0]), c0);
            c1 = fmaf(wj, fsigmoid(rv[3*j + 1]), c1);
            c2 = fmaf(wj, fsigmoid(rv[3*j + 2]), c2);
        }
    }

    // ---- 8. coalesced streaming weights store (linear smem -> STG.128.cs) ----
    {
        const float4* wsrc = reinterpret_cast<const float4*>(&sW[wi][0]);
        float4* wout = reinterpret_cast<float4*>(out + (long)5 * n_rays + base);
        __stcs(&wout[lane], wsrc[lane]);
        if (lane < 16) __stcs(&wout[32 + lane], wsrc[32 + lane]);
    }

    // ---- 9. warp reduce 5 scalars ----
    #pragma unroll
    for (int off = 16; off; off >>= 1) {
        acc += __shfl_xor_sync(FULLM, acc, off);
        dep += __shfl_xor_sync(FULLM, dep, off);
        c0  += __shfl_xor_sync(FULLM, c0,  off);
        c1  += __shfl_xor_sync(FULLM, c1,  off);
        c2  += __shfl_xor_sync(FULLM, c2,  off);
    }
    if (lane == 0) {
        out[(long)ray * 3 + 0] = c0;
        out[(long)ray * 3 + 1] = c1;
        out[(long)ray * 3 + 2] = c2;
        out[(long)3 * n_rays + ray] = dep;
        out[(long)4 * n_rays + ray] = acc;
    }
}

extern "C" void kernel_launch(void* const* d_in, const int* in_sizes, int n_in,
                              void* d_out, int out_size)
{
    const float* depth = (const float*)d_in[0];
    const float* rgb   = (const float*)d_in[1];
    const float* sigma = (const float*)d_in[2];
    float* out = (float*)d_out;

    const int n_rays = in_sizes[0] / NS;
    const int blocks = (n_rays + WPB - 1) / WPB;
    vr_kernel<<<blocks, 256>>>(depth, rgb, sigma, out, n_rays);
}